// round 16
// baseline (speedup 1.0000x reference)
#include <cuda_runtime.h>
#include <math.h>
#include <stdint.h>

// Problem constants
#define PD 3
#define ND 4096
#define FD 1024
#define HD 8
#define DD 8
#define EMB 64
#define ATTD 128
#define CD 16
#define MSEG 8          // m-dimension split (k2)
#define KSEG 8          // K split (k1)
#define KT 32           // m-chunk per ktile

// ---------------- scratch ----------------
__device__ __align__(16) float  g_fts [PD * ND * EMB];          // [p][n][h*8+d]
__device__ __align__(16) float  g_pk  [KSEG * PD * ND * EMB];   // k1 partials
__device__ __align__(16) float2 g_ab1 [PD * ND * HD];
__device__ __align__(16) float2 g_ab2 [PD * ND * HD];
__device__ __align__(16) float  g_part[MSEG * PD * ND * 72];    // 64 acc + 8 Z

// tf32 helpers (non-'a' PTX: works on compute_103)
__device__ __forceinline__ uint32_t to_tf32_rna(float f) {
    uint32_t r;
    asm("cvt.rna.tf32.f32 %0, %1;" : "=r"(r) : "f"(f));
    return r;
}
__device__ __forceinline__ float tf32_trunc(float f) {
    return __uint_as_float(__float_as_uint(f) & 0xFFFFE000u);
}
__device__ __forceinline__ void mma_tf32_16x8x8(float* d, uint32_t a0, uint32_t a1,
                                                uint32_t a2, uint32_t a3,
                                                uint32_t b0, uint32_t b1) {
    asm volatile(
        "mma.sync.aligned.m16n8k8.row.col.f32.tf32.tf32.f32 "
        "{%0,%1,%2,%3}, {%4,%5,%6,%7}, {%8,%9}, {%0,%1,%2,%3};"
        : "+f"(d[0]), "+f"(d[1]), "+f"(d[2]), "+f"(d[3])
        : "r"(a0), "r"(a1), "r"(a2), "r"(a3), "r"(b0), "r"(b1));
}
__device__ __forceinline__ float2 hilo(float x) {
    float hi = __uint_as_float(__float_as_uint(x) & 0xFFFFE000u);
    return make_float2(hi, x - hi);
}

// ---------------- K1: 3xTF32 mma projection GEMM, K-split, split accumulators -
__global__ __launch_bounds__(256) void k1_gemm(const float* __restrict__ inp,
                                               const float* __restrict__ W) {
    const int p    = blockIdx.y;
    const int n0   = blockIdx.x * 64;
    const int kseg = blockIdx.z;
    __shared__ float2 As2[64 * 36];   // [row][k] (hi,lo)
    __shared__ float2 Bs2[32 * 72];   // [k][col] (hi,lo)
    const int tid  = threadIdx.x;
    const int warp = tid >> 5, lane = tid & 31;
    const int g = lane >> 2, c = lane & 3;
    const int wrow = (warp >> 1) * 16;
    const int wcol = (warp & 1) * 32;

    float Dhh[4][4] = {};   // hi*hi chain
    float Dx [4][4] = {};   // hi*lo + lo*hi chain (independent)
    float4 ra[2], rb[2];
    const float* Wp = W + (size_t)p * HD * FD * DD;
    const int kbase = kseg * (FD / KSEG);

    #pragma unroll
    for (int it = 0; it < 2; it++) {
        int idx = it * 256 + tid;
        int row = idx >> 3, q = idx & 7;
        ra[it] = *reinterpret_cast<const float4*>(
            inp + ((size_t)(p * ND + n0 + row)) * FD + kbase + q * 4);
    }
    #pragma unroll
    for (int it = 0; it < 2; it++) {
        int idx = it * 256 + tid;
        int kk = idx >> 4, c4 = idx & 15;
        int head = c4 >> 1, d0 = (c4 & 1) * 4;
        rb[it] = *reinterpret_cast<const float4*>(
            Wp + (size_t)head * FD * DD + (size_t)(kbase + kk) * DD + d0);
    }

    for (int ch = 0; ch < (FD / KSEG) / 32; ch++) {
        if (ch) __syncthreads();
        #pragma unroll
        for (int it = 0; it < 2; it++) {
            int idx = it * 256 + tid;
            int row = idx >> 3, q = idx & 7;
            float v[4] = {ra[it].x, ra[it].y, ra[it].z, ra[it].w};
            #pragma unroll
            for (int j = 0; j < 4; j++)
                As2[row * 36 + q * 4 + j] = hilo(v[j]);
        }
        #pragma unroll
        for (int it = 0; it < 2; it++) {
            int idx = it * 256 + tid;
            int kk = idx >> 4, c4 = idx & 15;
            int col = (c4 >> 1) * 8 + (c4 & 1) * 4;
            float v[4] = {rb[it].x, rb[it].y, rb[it].z, rb[it].w};
            #pragma unroll
            for (int j = 0; j < 4; j++)
                Bs2[kk * 72 + col + j] = hilo(v[j]);
        }
        __syncthreads();
        if (ch < (FD / KSEG) / 32 - 1) {
            const int k0 = kbase + (ch + 1) * 32;
            #pragma unroll
            for (int it = 0; it < 2; it++) {
                int idx = it * 256 + tid;
                int row = idx >> 3, q = idx & 7;
                ra[it] = *reinterpret_cast<const float4*>(
                    inp + ((size_t)(p * ND + n0 + row)) * FD + k0 + q * 4);
            }
            #pragma unroll
            for (int it = 0; it < 2; it++) {
                int idx = it * 256 + tid;
                int kk = idx >> 4, c4 = idx & 15;
                int head = c4 >> 1, d0 = (c4 & 1) * 4;
                rb[it] = *reinterpret_cast<const float4*>(
                    Wp + (size_t)head * FD * DD + (size_t)(k0 + kk) * DD + d0);
            }
        }
        #pragma unroll
        for (int kk8 = 0; kk8 < 4; kk8++) {
            const int kb = kk8 * 8;
            float2 a0p = As2[(wrow + g) * 36 + kb + c];
            float2 a1p = As2[(wrow + g + 8) * 36 + kb + c];
            float2 a2p = As2[(wrow + g) * 36 + kb + c + 4];
            float2 a3p = As2[(wrow + g + 8) * 36 + kb + c + 4];
            #pragma unroll
            for (int nt = 0; nt < 4; nt++) {
                const int col = wcol + nt * 8 + g;
                float2 b0p = Bs2[(kb + c) * 72 + col];
                float2 b1p = Bs2[(kb + c + 4) * 72 + col];
                mma_tf32_16x8x8(Dhh[nt], __float_as_uint(a0p.x), __float_as_uint(a1p.x),
                                __float_as_uint(a2p.x), __float_as_uint(a3p.x),
                                __float_as_uint(b0p.x), __float_as_uint(b1p.x));
                mma_tf32_16x8x8(Dx[nt], __float_as_uint(a0p.x), __float_as_uint(a1p.x),
                                __float_as_uint(a2p.x), __float_as_uint(a3p.x),
                                __float_as_uint(b0p.y), __float_as_uint(b1p.y));
                mma_tf32_16x8x8(Dx[nt], __float_as_uint(a0p.y), __float_as_uint(a1p.y),
                                __float_as_uint(a2p.y), __float_as_uint(a3p.y),
                                __float_as_uint(b0p.x), __float_as_uint(b1p.x));
            }
        }
    }

    float* pk = g_pk + ((size_t)(kseg * PD + p) * ND + n0) * EMB;
    #pragma unroll
    for (int nt = 0; nt < 4; nt++) {
        int col = wcol + nt * 8 + 2 * c;
        int r0 = wrow + g, r1 = wrow + g + 8;
        *reinterpret_cast<float2*>(pk + (size_t)r0 * EMB + col) =
            make_float2(Dhh[nt][0] + Dx[nt][0], Dhh[nt][1] + Dx[nt][1]);
        *reinterpret_cast<float2*>(pk + (size_t)r1 * EMB + col) =
            make_float2(Dhh[nt][2] + Dx[nt][2], Dhh[nt][3] + Dx[nt][3]);
    }
}

// ---------------- K1c: combine K-split partials + factor epilogue -------------
__global__ __launch_bounds__(256) void k1c_combine(const float* __restrict__ a1w,
                                                   const float* __restrict__ a1b,
                                                   const float* __restrict__ a2w,
                                                   const float* __restrict__ a2b) {
    const int p  = blockIdx.y;
    const int n0 = blockIdx.x * 32;
    const int tid = threadIdx.x;
    __shared__ float Cs[32 * 65];
    const int r = tid >> 3, q = tid & 7;

    float4 s0 = make_float4(0.f, 0.f, 0.f, 0.f);
    float4 s1 = s0;
    #pragma unroll
    for (int seg = 0; seg < KSEG; seg++) {
        const float* pk = g_pk + ((size_t)(seg * PD + p) * ND + n0 + r) * EMB + q * 8;
        float4 v0 = *reinterpret_cast<const float4*>(pk);
        float4 v1 = *reinterpret_cast<const float4*>(pk + 4);
        s0.x += v0.x; s0.y += v0.y; s0.z += v0.z; s0.w += v0.w;
        s1.x += v1.x; s1.y += v1.y; s1.z += v1.z; s1.w += v1.w;
    }
    float* f = g_fts + ((size_t)(p * ND + n0 + r)) * EMB + q * 8;
    *reinterpret_cast<float4*>(f)     = s0;
    *reinterpret_cast<float4*>(f + 4) = s1;
    Cs[r * 65 + q * 8 + 0] = s0.x; Cs[r * 65 + q * 8 + 1] = s0.y;
    Cs[r * 65 + q * 8 + 2] = s0.z; Cs[r * 65 + q * 8 + 3] = s0.w;
    Cs[r * 65 + q * 8 + 4] = s1.x; Cs[r * 65 + q * 8 + 5] = s1.y;
    Cs[r * 65 + q * 8 + 6] = s1.z; Cs[r * 65 + q * 8 + 7] = s1.w;
    __syncthreads();

    const int hh = tid & 7;
    const float* fr = Cs + r * 65 + hh * 8;
    const float* w1 = a1w + (size_t)(p * HD + hh) * DD;
    const float* w2 = a2w + (size_t)(p * HD + hh) * DD;
    float f1 = a1b[p * HD + hh];
    float f2 = a2b[p * HD + hh];
    #pragma unroll
    for (int d = 0; d < 8; d++) { f1 += fr[d] * w1[d]; f2 += fr[d] * w2[d]; }
    g_ab1[((size_t)p * ND + n0 + r) * HD + hh] = make_float2(__expf(f1), __expf(0.01f * f1));
    g_ab2[((size_t)p * ND + n0 + r) * HD + hh] = make_float2(__expf(f2), __expf(0.01f * f2));
}

// ---------------- K2: mma.sync tf32 attention, 3 CTAs/SM ----------------------
// x-factors in smem (kt-invariant), double-buffered tiles, one sync/ktile.
#define EBSTR 20   // float2 row stride for eb pairs
#define EB_BUF   (128 * EBSTR)            // float2 per buffer
#define FTS_BUF  (32 * 72)                // float per buffer
#define F2_BUF   (32 * 9)                 // float2 per buffer
#define AB1_SZ   (128 * 9)                // float2, single buffer
#define K2_SMEM  (2 * EB_BUF * 8 + 2 * FTS_BUF * 4 + 2 * F2_BUF * 8 + AB1_SZ * 8)

extern __shared__ char k2smem[];

__global__ __launch_bounds__(256, 3) void k2_attn_mma(const float* __restrict__ bias) {
    const int p    = blockIdx.z;
    const int mseg = blockIdx.y;
    const int n0   = blockIdx.x * 128;
    const int tid  = threadIdx.x;
    const int h    = tid >> 5;          // warp = head
    const int lane = tid & 31;
    const int g = lane >> 2, c = lane & 3;

    float2* eb_base  = reinterpret_cast<float2*>(k2smem);
    float*  fts_base = reinterpret_cast<float*>(k2smem + 2 * EB_BUF * 8);
    float2* f2_base  = reinterpret_cast<float2*>(k2smem + 2 * EB_BUF * 8 + 2 * FTS_BUF * 4);
    float2* ab1_s    = reinterpret_cast<float2*>(k2smem + 2 * EB_BUF * 8 + 2 * FTS_BUF * 4
                                                 + 2 * F2_BUF * 8);

    float D[8][4];
    float sum0[8], sum1[8];
    #pragma unroll
    for (int nt = 0; nt < 8; nt++) {
        D[nt][0] = D[nt][1] = D[nt][2] = D[nt][3] = 0.f;
        sum0[nt] = sum1[nt] = 0.f;
    }

    // stage (A1,B1) factors once (kt-invariant)
    for (int i = tid; i < 128 * 8; i += 256) {
        int n = i >> 3, hh = i & 7;
        ab1_s[n * 9 + hh] = g_ab1[((size_t)p * ND + n0 + n) * HD + hh];
    }

    const float* brow = bias + ((size_t)p * ND + n0) * ND;
    const int n_loc = tid >> 1, kh = tid & 1;
    const int m_base = mseg * (ND / MSEG);
    const int NKT = (ND / MSEG) / KT;

    // bias prefetch registers (first half of this thread's slice)
    float4 pb0, pb1;
    {
        const float* bp = brow + (size_t)n_loc * ND + m_base + kh * 16;
        pb0 = *reinterpret_cast<const float4*>(bp);
        pb1 = *reinterpret_cast<const float4*>(bp + 4);
    }

    for (int kt = 0; kt < NKT; kt++) {
        const int m0 = m_base + kt * KT;
        const int buf = kt & 1;
        float2* eb_s  = eb_base + buf * EB_BUF;
        float*  fts_s = fts_base + buf * FTS_BUF;
        float2* f2_s  = f2_base + buf * F2_BUF;

        // stage exp(bias) pairs (pb0/pb1 prefetched; pb2/pb3 loaded here)
        {
            const float* bp = brow + (size_t)n_loc * ND + m0 + kh * 16;
            float4 pb2 = *reinterpret_cast<const float4*>(bp + 8);
            float4 pb3 = *reinterpret_cast<const float4*>(bp + 12);
            float e[16];
            e[0] = __expf(pb0.x); e[1] = __expf(pb0.y);
            e[2] = __expf(pb0.z); e[3] = __expf(pb0.w);
            e[4] = __expf(pb1.x); e[5] = __expf(pb1.y);
            e[6] = __expf(pb1.z); e[7] = __expf(pb1.w);
            e[8]  = __expf(pb2.x); e[9]  = __expf(pb2.y);
            e[10] = __expf(pb2.z); e[11] = __expf(pb2.w);
            e[12] = __expf(pb3.x); e[13] = __expf(pb3.y);
            e[14] = __expf(pb3.z); e[15] = __expf(pb3.w);
            float2* pe = eb_s + n_loc * EBSTR + kh * 8;
            #pragma unroll
            for (int sl = 0; sl < 2; sl++)
                #pragma unroll
                for (int cc = 0; cc < 4; cc++)
                    pe[sl * 4 + cc] = make_float2(e[sl * 8 + cc], e[sl * 8 + cc + 4]);
        }
        // stage fts tile (32 m x 64 d), rounded to tf32
        #pragma unroll
        for (int it = 0; it < 2; it++) {
            int idx = it * 256 + tid;
            int mm = idx >> 4, q = idx & 15;
            float4 v = *reinterpret_cast<const float4*>(
                g_fts + ((size_t)(p * ND + m0 + mm)) * EMB + q * 4);
            uint32_t* dst = (uint32_t*)&fts_s[mm * 72 + q * 4];
            dst[0] = to_tf32_rna(v.x); dst[1] = to_tf32_rna(v.y);
            dst[2] = to_tf32_rna(v.z); dst[3] = to_tf32_rna(v.w);
        }
        {
            int mm = tid >> 3, hh = tid & 7;
            f2_s[mm * 9 + hh] = g_ab2[((size_t)p * ND + m0 + mm) * HD + hh];
        }
        __syncthreads();
        // prefetch next ktile's first 8 bias values (overlaps compute below)
        if (kt + 1 < NKT) {
            const float* bp = brow + (size_t)n_loc * ND + m0 + KT + kh * 16;
            pb0 = *reinterpret_cast<const float4*>(bp);
            pb1 = *reinterpret_cast<const float4*>(bp + 4);
        }

        #pragma unroll
        for (int s = 0; s < 4; s++) {
            const int mlo = s * 8 + c;
            uint32_t b0 = __float_as_uint(fts_s[mlo * 72 + h * 8 + g]);
            uint32_t b1 = __float_as_uint(fts_s[(mlo + 4) * 72 + h * 8 + g]);
            float2 ylo = f2_s[mlo * 9 + h];
            float2 yhi = f2_s[(mlo + 4) * 9 + h];
            const float2* pe = eb_s + s * 4 + c;

            #pragma unroll
            for (int nt = 0; nt < 8; nt++) {
                float2 x0 = ab1_s[(nt * 16 + g) * 9 + h];
                float2 x1 = ab1_s[(nt * 16 + 8 + g) * 9 + h];
                float2 e0 = pe[(nt * 16 + g) * EBSTR];       // (e[n][mlo], e[n][mlo+4])
                float2 e1 = pe[(nt * 16 + 8 + g) * EBSTR];   // row n+8
                float w0 = tf32_trunc(fmaxf(x0.x * ylo.x, x0.y * ylo.y) * e0.x);
                float w2 = tf32_trunc(fmaxf(x0.x * yhi.x, x0.y * yhi.y) * e0.y);
                float w1 = tf32_trunc(fmaxf(x1.x * ylo.x, x1.y * ylo.y) * e1.x);
                float w3 = tf32_trunc(fmaxf(x1.x * yhi.x, x1.y * yhi.y) * e1.y);
                sum0[nt] += w0 + w2;
                sum1[nt] += w1 + w3;
                mma_tf32_16x8x8(D[nt], __float_as_uint(w0), __float_as_uint(w1),
                                __float_as_uint(w2), __float_as_uint(w3), b0, b1);
            }
        }
    }

    #pragma unroll
    for (int nt = 0; nt < 8; nt++) {
        float s0 = sum0[nt], s1 = sum1[nt];
        s0 += __shfl_xor_sync(0xffffffffu, s0, 1);
        s0 += __shfl_xor_sync(0xffffffffu, s0, 2);
        s1 += __shfl_xor_sync(0xffffffffu, s1, 1);
        s1 += __shfl_xor_sync(0xffffffffu, s1, 2);
        int r0 = n0 + nt * 16 + g, r1 = r0 + 8;
        float* op0 = g_part + (((size_t)mseg * PD + p) * ND + r0) * 72;
        float* op1 = g_part + (((size_t)mseg * PD + p) * ND + r1) * 72;
        *reinterpret_cast<float2*>(op0 + h * 8 + 2 * c) = make_float2(D[nt][0], D[nt][1]);
        *reinterpret_cast<float2*>(op1 + h * 8 + 2 * c) = make_float2(D[nt][2], D[nt][3]);
        if (c == 0) { op0[64 + h] = s0; op1[64 + h] = s1; }
    }
}

// ---------------- K3: combine + ELU + semantic attention + classifier ---------
__global__ __launch_bounds__(128) void k3_final(const float* __restrict__ h_bias,
                                                const float* __restrict__ Ws,
                                                const float* __restrict__ bsv,
                                                const float* __restrict__ u,
                                                const float* __restrict__ Wc,
                                                const float* __restrict__ bc,
                                                float* __restrict__ out,
                                                int has_final, int has_alpha) {
    const int n = blockIdx.x;
    const int t = threadIdx.x;
    __shared__ float multi_s[PD][EMB];
    __shared__ float red[4 * PD];
    __shared__ float al[PD];
    __shared__ float fin[EMB];

    for (int idx = t; idx < PD * EMB; idx += 128) {
        int p = idx / EMB, d = idx % EMB, h = d >> 3;
        float a = 0.f, Z = 0.f;
        #pragma unroll
        for (int s = 0; s < MSEG; s++) {
            const float* b = g_part + (((size_t)s * PD + p) * ND + n) * 72;
            a += b[d];
            Z += b[64 + h];
        }
        float val = a / Z + h_bias[(p * HD + h) * DD + (d & 7)];
        multi_s[p][d] = val > 0.f ? val : expm1f(val);
    }
    __syncthreads();

    float partial[PD];
    #pragma unroll
    for (int p = 0; p < PD; p++) {
        float s = bsv[t];
        #pragma unroll
        for (int d = 0; d < EMB; d++) s += multi_s[p][d] * Ws[d * ATTD + t];
        partial[p] = tanhf(s) * u[t];
    }
    #pragma unroll
    for (int p = 0; p < PD; p++) {
        float v = partial[p];
        #pragma unroll
        for (int o = 16; o > 0; o >>= 1) v += __shfl_down_sync(0xffffffffu, v, o);
        if ((t & 31) == 0) red[(t >> 5) * PD + p] = v;
    }
    __syncthreads();
    if (t == 0) {
        float sc[PD];
        #pragma unroll
        for (int p = 0; p < PD; p++)
            sc[p] = red[p] + red[PD + p] + red[2 * PD + p] + red[3 * PD + p];
        float mx = fmaxf(sc[0], fmaxf(sc[1], sc[2]));
        float e0 = __expf(sc[0] - mx), e1 = __expf(sc[1] - mx), e2 = __expf(sc[2] - mx);
        float Zs = e0 + e1 + e2;
        al[0] = e0 / Zs; al[1] = e1 / Zs; al[2] = e2 / Zs;
    }
    __syncthreads();

    if (has_alpha && t < PD)
        out[(size_t)ND * (CD + EMB) + (size_t)n * PD + t] = al[t];

    if (t < EMB) {
        float f = al[0] * multi_s[0][t] + al[1] * multi_s[1][t] + al[2] * multi_s[2][t];
        fin[t] = f;
        if (has_final) out[(size_t)ND * CD + (size_t)n * EMB + t] = f;
    }
    __syncthreads();

    if (t < CD) {
        float s = bc[t];
        #pragma unroll
        for (int d = 0; d < EMB; d++) s += fin[d] * Wc[d * CD + t];
        out[(size_t)n * CD + t] = s;
    }
}

// ---------------- launch ------------------------------------------------------
extern "C" void kernel_launch(void* const* d_in, const int* in_sizes, int n_in,
                              void* d_out, int out_size) {
    const float* inputs   = (const float*)d_in[0];
    const float* bias_mat = (const float*)d_in[1];
    const float* W        = (const float*)d_in[2];
    const float* a1_w     = (const float*)d_in[3];
    const float* a1_b     = (const float*)d_in[4];
    const float* a2_w     = (const float*)d_in[5];
    const float* a2_b     = (const float*)d_in[6];
    const float* h_bias   = (const float*)d_in[7];
    const float* Ws       = (const float*)d_in[8];
    const float* bs       = (const float*)d_in[9];
    const float* u        = (const float*)d_in[10];
    const float* Wc       = (const float*)d_in[11];
    const float* bc       = (const float*)d_in[12];
    float* out = (float*)d_out;

    int has_final = (out_size >= ND * (CD + EMB)) ? 1 : 0;
    int has_alpha = (out_size >= ND * (CD + EMB + PD)) ? 1 : 0;

    cudaFuncSetAttribute(k2_attn_mma, cudaFuncAttributeMaxDynamicSharedMemorySize,
                         K2_SMEM);

    k1_gemm    <<<dim3(ND / 64, PD, KSEG), 256>>>(inputs, W);
    k1c_combine<<<dim3(ND / 32, PD), 256>>>(a1_w, a1_b, a2_w, a2_b);
    k2_attn_mma<<<dim3(ND / 128, MSEG, PD), 256, K2_SMEM>>>(bias_mat);
    k3_final   <<<ND, 128>>>(h_bias, Ws, bs, u, Wc, bc, out, has_final, has_alpha);
    (void)in_sizes; (void)n_in;
}

// round 17
// speedup vs baseline: 1.7591x; 1.7591x over previous
#include <cuda_runtime.h>
#include <math.h>
#include <stdint.h>

// Problem constants
#define PD 3
#define ND 4096
#define FD 1024
#define HD 8
#define DD 8
#define EMB 64
#define ATTD 128
#define CD 16
#define MSEG 8          // m-dimension split (k2)
#define KSEG 8          // K split (k1)
#define KT 32           // m-chunk per ktile

// ---------------- scratch ----------------
__device__ __align__(16) float  g_fts [PD * ND * EMB];          // [p][n][h*8+d]
__device__ __align__(16) float  g_pk  [KSEG * PD * ND * EMB];   // k1 partials
__device__ __align__(16) float2 g_ab1 [PD * ND * HD];
__device__ __align__(16) float2 g_ab2 [PD * ND * HD];
__device__ __align__(16) float  g_part[MSEG * PD * ND * 72];    // 64 acc + 8 Z

// tf32 helpers (non-'a' PTX: works on compute_103)
__device__ __forceinline__ uint32_t to_tf32_rna(float f) {
    uint32_t r;
    asm("cvt.rna.tf32.f32 %0, %1;" : "=r"(r) : "f"(f));
    return r;
}
__device__ __forceinline__ float tf32_trunc(float f) {
    return __uint_as_float(__float_as_uint(f) & 0xFFFFE000u);
}
__device__ __forceinline__ void mma_tf32_16x8x8(float* d, uint32_t a0, uint32_t a1,
                                                uint32_t a2, uint32_t a3,
                                                uint32_t b0, uint32_t b1) {
    asm volatile(
        "mma.sync.aligned.m16n8k8.row.col.f32.tf32.tf32.f32 "
        "{%0,%1,%2,%3}, {%4,%5,%6,%7}, {%8,%9}, {%0,%1,%2,%3};"
        : "+f"(d[0]), "+f"(d[1]), "+f"(d[2]), "+f"(d[3])
        : "r"(a0), "r"(a1), "r"(a2), "r"(a3), "r"(b0), "r"(b1));
}
__device__ __forceinline__ float2 hilo(float x) {
    float hi = __uint_as_float(__float_as_uint(x) & 0xFFFFE000u);
    return make_float2(hi, x - hi);
}

// ---------------- K1: 2xTF32 mma projection GEMM (hi*hi + hi*lo), K-split -----
__global__ __launch_bounds__(256) void k1_gemm(const float* __restrict__ inp,
                                               const float* __restrict__ W) {
    const int p    = blockIdx.y;
    const int n0   = blockIdx.x * 64;
    const int kseg = blockIdx.z;
    __shared__ float2 As2[64 * 36];   // [row][k] (hi,lo)
    __shared__ float2 Bs2[32 * 72];   // [k][col] (hi,lo)
    const int tid  = threadIdx.x;
    const int warp = tid >> 5, lane = tid & 31;
    const int g = lane >> 2, c = lane & 3;
    const int wrow = (warp >> 1) * 16;
    const int wcol = (warp & 1) * 32;

    float Dhh[4][4] = {};   // hi*hi chain
    float Dx [4][4] = {};   // hi_A*lo_B chain (lo_A*hi_B dropped: rel err ~2^-11, OK)
    float4 ra[2], rb[2];
    const float* Wp = W + (size_t)p * HD * FD * DD;
    const int kbase = kseg * (FD / KSEG);

    #pragma unroll
    for (int it = 0; it < 2; it++) {
        int idx = it * 256 + tid;
        int row = idx >> 3, q = idx & 7;
        ra[it] = *reinterpret_cast<const float4*>(
            inp + ((size_t)(p * ND + n0 + row)) * FD + kbase + q * 4);
    }
    #pragma unroll
    for (int it = 0; it < 2; it++) {
        int idx = it * 256 + tid;
        int kk = idx >> 4, c4 = idx & 15;
        int head = c4 >> 1, d0 = (c4 & 1) * 4;
        rb[it] = *reinterpret_cast<const float4*>(
            Wp + (size_t)head * FD * DD + (size_t)(kbase + kk) * DD + d0);
    }

    for (int ch = 0; ch < (FD / KSEG) / 32; ch++) {
        if (ch) __syncthreads();
        #pragma unroll
        for (int it = 0; it < 2; it++) {
            int idx = it * 256 + tid;
            int row = idx >> 3, q = idx & 7;
            float v[4] = {ra[it].x, ra[it].y, ra[it].z, ra[it].w};
            #pragma unroll
            for (int j = 0; j < 4; j++)
                As2[row * 36 + q * 4 + j] = hilo(v[j]);
        }
        #pragma unroll
        for (int it = 0; it < 2; it++) {
            int idx = it * 256 + tid;
            int kk = idx >> 4, c4 = idx & 15;
            int col = (c4 >> 1) * 8 + (c4 & 1) * 4;
            float v[4] = {rb[it].x, rb[it].y, rb[it].z, rb[it].w};
            #pragma unroll
            for (int j = 0; j < 4; j++)
                Bs2[kk * 72 + col + j] = hilo(v[j]);
        }
        __syncthreads();
        if (ch < (FD / KSEG) / 32 - 1) {
            const int k0 = kbase + (ch + 1) * 32;
            #pragma unroll
            for (int it = 0; it < 2; it++) {
                int idx = it * 256 + tid;
                int row = idx >> 3, q = idx & 7;
                ra[it] = *reinterpret_cast<const float4*>(
                    inp + ((size_t)(p * ND + n0 + row)) * FD + k0 + q * 4);
            }
            #pragma unroll
            for (int it = 0; it < 2; it++) {
                int idx = it * 256 + tid;
                int kk = idx >> 4, c4 = idx & 15;
                int head = c4 >> 1, d0 = (c4 & 1) * 4;
                rb[it] = *reinterpret_cast<const float4*>(
                    Wp + (size_t)head * FD * DD + (size_t)(k0 + kk) * DD + d0);
            }
        }
        #pragma unroll
        for (int kk8 = 0; kk8 < 4; kk8++) {
            const int kb = kk8 * 8;
            float2 a0p = As2[(wrow + g) * 36 + kb + c];
            float2 a1p = As2[(wrow + g + 8) * 36 + kb + c];
            float2 a2p = As2[(wrow + g) * 36 + kb + c + 4];
            float2 a3p = As2[(wrow + g + 8) * 36 + kb + c + 4];
            #pragma unroll
            for (int nt = 0; nt < 4; nt++) {
                const int col = wcol + nt * 8 + g;
                float2 b0p = Bs2[(kb + c) * 72 + col];
                float2 b1p = Bs2[(kb + c + 4) * 72 + col];
                mma_tf32_16x8x8(Dhh[nt], __float_as_uint(a0p.x), __float_as_uint(a1p.x),
                                __float_as_uint(a2p.x), __float_as_uint(a3p.x),
                                __float_as_uint(b0p.x), __float_as_uint(b1p.x));
                mma_tf32_16x8x8(Dx[nt], __float_as_uint(a0p.x), __float_as_uint(a1p.x),
                                __float_as_uint(a2p.x), __float_as_uint(a3p.x),
                                __float_as_uint(b0p.y), __float_as_uint(b1p.y));
            }
        }
    }

    float* pk = g_pk + ((size_t)(kseg * PD + p) * ND + n0) * EMB;
    #pragma unroll
    for (int nt = 0; nt < 4; nt++) {
        int col = wcol + nt * 8 + 2 * c;
        int r0 = wrow + g, r1 = wrow + g + 8;
        *reinterpret_cast<float2*>(pk + (size_t)r0 * EMB + col) =
            make_float2(Dhh[nt][0] + Dx[nt][0], Dhh[nt][1] + Dx[nt][1]);
        *reinterpret_cast<float2*>(pk + (size_t)r1 * EMB + col) =
            make_float2(Dhh[nt][2] + Dx[nt][2], Dhh[nt][3] + Dx[nt][3]);
    }
}

// ---------------- K1c: combine K-split partials + factor epilogue -------------
__global__ __launch_bounds__(256) void k1c_combine(const float* __restrict__ a1w,
                                                   const float* __restrict__ a1b,
                                                   const float* __restrict__ a2w,
                                                   const float* __restrict__ a2b) {
    const int p  = blockIdx.y;
    const int n0 = blockIdx.x * 32;
    const int tid = threadIdx.x;
    __shared__ float Cs[32 * 65];
    const int r = tid >> 3, q = tid & 7;

    float4 s0 = make_float4(0.f, 0.f, 0.f, 0.f);
    float4 s1 = s0;
    #pragma unroll
    for (int seg = 0; seg < KSEG; seg++) {
        const float* pk = g_pk + ((size_t)(seg * PD + p) * ND + n0 + r) * EMB + q * 8;
        float4 v0 = *reinterpret_cast<const float4*>(pk);
        float4 v1 = *reinterpret_cast<const float4*>(pk + 4);
        s0.x += v0.x; s0.y += v0.y; s0.z += v0.z; s0.w += v0.w;
        s1.x += v1.x; s1.y += v1.y; s1.z += v1.z; s1.w += v1.w;
    }
    float* f = g_fts + ((size_t)(p * ND + n0 + r)) * EMB + q * 8;
    *reinterpret_cast<float4*>(f)     = s0;
    *reinterpret_cast<float4*>(f + 4) = s1;
    Cs[r * 65 + q * 8 + 0] = s0.x; Cs[r * 65 + q * 8 + 1] = s0.y;
    Cs[r * 65 + q * 8 + 2] = s0.z; Cs[r * 65 + q * 8 + 3] = s0.w;
    Cs[r * 65 + q * 8 + 4] = s1.x; Cs[r * 65 + q * 8 + 5] = s1.y;
    Cs[r * 65 + q * 8 + 6] = s1.z; Cs[r * 65 + q * 8 + 7] = s1.w;
    __syncthreads();

    const int hh = tid & 7;
    const float* fr = Cs + r * 65 + hh * 8;
    const float* w1 = a1w + (size_t)(p * HD + hh) * DD;
    const float* w2 = a2w + (size_t)(p * HD + hh) * DD;
    float f1 = a1b[p * HD + hh];
    float f2 = a2b[p * HD + hh];
    #pragma unroll
    for (int d = 0; d < 8; d++) { f1 += fr[d] * w1[d]; f2 += fr[d] * w2[d]; }
    g_ab1[((size_t)p * ND + n0 + r) * HD + hh] = make_float2(__expf(f1), __expf(0.01f * f1));
    g_ab2[((size_t)p * ND + n0 + r) * HD + hh] = make_float2(__expf(f2), __expf(0.01f * f2));
}

// ---------------- K2: mma.sync tf32 attention (R15 best: double-buffer) -------
#define EBSTR 20   // float2 row stride for eb pairs
#define EB_BUF   (128 * EBSTR)            // float2 per buffer
#define FTS_BUF  (32 * 72)                // float per buffer
#define F2_BUF   (32 * 9)                 // float2 per buffer
#define K2_SMEM  (2 * EB_BUF * 8 + 2 * FTS_BUF * 4 + 2 * F2_BUF * 8)

extern __shared__ char k2smem[];

__global__ __launch_bounds__(256, 2) void k2_attn_mma(const float* __restrict__ bias) {
    const int p    = blockIdx.z;
    const int mseg = blockIdx.y;
    const int n0   = blockIdx.x * 128;
    const int tid  = threadIdx.x;
    const int h    = tid >> 5;          // warp = head
    const int lane = tid & 31;
    const int g = lane >> 2, c = lane & 3;

    float2* eb_base  = reinterpret_cast<float2*>(k2smem);
    float*  fts_base = reinterpret_cast<float*>(k2smem + 2 * EB_BUF * 8);
    float2* f2_base  = reinterpret_cast<float2*>(k2smem + 2 * EB_BUF * 8 + 2 * FTS_BUF * 4);

    float D[8][4];
    float sum0[8], sum1[8];
    float2 x0[8], x1[8];
    #pragma unroll
    for (int nt = 0; nt < 8; nt++) {
        D[nt][0] = D[nt][1] = D[nt][2] = D[nt][3] = 0.f;
        sum0[nt] = sum1[nt] = 0.f;
        x0[nt] = g_ab1[((size_t)p * ND + n0 + nt * 16 + g) * HD + h];
        x1[nt] = g_ab1[((size_t)p * ND + n0 + nt * 16 + 8 + g) * HD + h];
    }

    const float* brow = bias + ((size_t)p * ND + n0) * ND;
    const int n_loc = tid >> 1, kh = tid & 1;
    const int m_base = mseg * (ND / MSEG);
    const int NKT = (ND / MSEG) / KT;

    float4 pb0, pb1;
    {
        const float* bp = brow + (size_t)n_loc * ND + m_base + kh * 16;
        pb0 = *reinterpret_cast<const float4*>(bp);
        pb1 = *reinterpret_cast<const float4*>(bp + 4);
    }

    for (int kt = 0; kt < NKT; kt++) {
        const int m0 = m_base + kt * KT;
        const int buf = kt & 1;
        float2* eb_s  = eb_base + buf * EB_BUF;
        float*  fts_s = fts_base + buf * FTS_BUF;
        float2* f2_s  = f2_base + buf * F2_BUF;

        {
            const float* bp = brow + (size_t)n_loc * ND + m0 + kh * 16;
            float4 pb2 = *reinterpret_cast<const float4*>(bp + 8);
            float4 pb3 = *reinterpret_cast<const float4*>(bp + 12);
            float e[16];
            e[0] = __expf(pb0.x); e[1] = __expf(pb0.y);
            e[2] = __expf(pb0.z); e[3] = __expf(pb0.w);
            e[4] = __expf(pb1.x); e[5] = __expf(pb1.y);
            e[6] = __expf(pb1.z); e[7] = __expf(pb1.w);
            e[8]  = __expf(pb2.x); e[9]  = __expf(pb2.y);
            e[10] = __expf(pb2.z); e[11] = __expf(pb2.w);
            e[12] = __expf(pb3.x); e[13] = __expf(pb3.y);
            e[14] = __expf(pb3.z); e[15] = __expf(pb3.w);
            float2* pe = eb_s + n_loc * EBSTR + kh * 8;
            #pragma unroll
            for (int sl = 0; sl < 2; sl++)
                #pragma unroll
                for (int cc = 0; cc < 4; cc++)
                    pe[sl * 4 + cc] = make_float2(e[sl * 8 + cc], e[sl * 8 + cc + 4]);
        }
        #pragma unroll
        for (int it = 0; it < 2; it++) {
            int idx = it * 256 + tid;
            int mm = idx >> 4, q = idx & 15;
            float4 v = *reinterpret_cast<const float4*>(
                g_fts + ((size_t)(p * ND + m0 + mm)) * EMB + q * 4);
            uint32_t* dst = (uint32_t*)&fts_s[mm * 72 + q * 4];
            dst[0] = to_tf32_rna(v.x); dst[1] = to_tf32_rna(v.y);
            dst[2] = to_tf32_rna(v.z); dst[3] = to_tf32_rna(v.w);
        }
        {
            int mm = tid >> 3, hh = tid & 7;
            f2_s[mm * 9 + hh] = g_ab2[((size_t)p * ND + m0 + mm) * HD + hh];
        }
        __syncthreads();
        if (kt + 1 < NKT) {
            const float* bp = brow + (size_t)n_loc * ND + m0 + KT + kh * 16;
            pb0 = *reinterpret_cast<const float4*>(bp);
            pb1 = *reinterpret_cast<const float4*>(bp + 4);
        }

        #pragma unroll
        for (int s = 0; s < 4; s++) {
            const int mlo = s * 8 + c;
            uint32_t b0 = __float_as_uint(fts_s[mlo * 72 + h * 8 + g]);
            uint32_t b1 = __float_as_uint(fts_s[(mlo + 4) * 72 + h * 8 + g]);
            float2 ylo = f2_s[mlo * 9 + h];
            float2 yhi = f2_s[(mlo + 4) * 9 + h];
            const float2* pe = eb_s + s * 4 + c;

            #pragma unroll
            for (int nt = 0; nt < 8; nt++) {
                float2 e0 = pe[(nt * 16 + g) * EBSTR];
                float2 e1 = pe[(nt * 16 + 8 + g) * EBSTR];
                float w0 = tf32_trunc(fmaxf(x0[nt].x * ylo.x, x0[nt].y * ylo.y) * e0.x);
                float w2 = tf32_trunc(fmaxf(x0[nt].x * yhi.x, x0[nt].y * yhi.y) * e0.y);
                float w1 = tf32_trunc(fmaxf(x1[nt].x * ylo.x, x1[nt].y * ylo.y) * e1.x);
                float w3 = tf32_trunc(fmaxf(x1[nt].x * yhi.x, x1[nt].y * yhi.y) * e1.y);
                sum0[nt] += w0 + w2;
                sum1[nt] += w1 + w3;
                mma_tf32_16x8x8(D[nt], __float_as_uint(w0), __float_as_uint(w1),
                                __float_as_uint(w2), __float_as_uint(w3), b0, b1);
            }
        }
    }

    #pragma unroll
    for (int nt = 0; nt < 8; nt++) {
        float s0 = sum0[nt], s1 = sum1[nt];
        s0 += __shfl_xor_sync(0xffffffffu, s0, 1);
        s0 += __shfl_xor_sync(0xffffffffu, s0, 2);
        s1 += __shfl_xor_sync(0xffffffffu, s1, 1);
        s1 += __shfl_xor_sync(0xffffffffu, s1, 2);
        int r0 = n0 + nt * 16 + g, r1 = r0 + 8;
        float* op0 = g_part + (((size_t)mseg * PD + p) * ND + r0) * 72;
        float* op1 = g_part + (((size_t)mseg * PD + p) * ND + r1) * 72;
        *reinterpret_cast<float2*>(op0 + h * 8 + 2 * c) = make_float2(D[nt][0], D[nt][1]);
        *reinterpret_cast<float2*>(op1 + h * 8 + 2 * c) = make_float2(D[nt][2], D[nt][3]);
        if (c == 0) { op0[64 + h] = s0; op1[64 + h] = s1; }
    }
}

// ---------------- K3: combine + ELU + semantic attention + classifier ---------
__global__ __launch_bounds__(128) void k3_final(const float* __restrict__ h_bias,
                                                const float* __restrict__ Ws,
                                                const float* __restrict__ bsv,
                                                const float* __restrict__ u,
                                                const float* __restrict__ Wc,
                                                const float* __restrict__ bc,
                                                float* __restrict__ out,
                                                int has_final, int has_alpha) {
    const int n = blockIdx.x;
    const int t = threadIdx.x;
    __shared__ float multi_s[PD][EMB];
    __shared__ float red[4 * PD];
    __shared__ float al[PD];
    __shared__ float fin[EMB];

    for (int idx = t; idx < PD * EMB; idx += 128) {
        int p = idx / EMB, d = idx % EMB, h = d >> 3;
        float a = 0.f, Z = 0.f;
        #pragma unroll
        for (int s = 0; s < MSEG; s++) {
            const float* b = g_part + (((size_t)s * PD + p) * ND + n) * 72;
            a += b[d];
            Z += b[64 + h];
        }
        float val = a / Z + h_bias[(p * HD + h) * DD + (d & 7)];
        multi_s[p][d] = val > 0.f ? val : expm1f(val);
    }
    __syncthreads();

    float partial[PD];
    #pragma unroll
    for (int p = 0; p < PD; p++) {
        float s = bsv[t];
        #pragma unroll
        for (int d = 0; d < EMB; d++) s += multi_s[p][d] * Ws[d * ATTD + t];
        partial[p] = tanhf(s) * u[t];
    }
    #pragma unroll
    for (int p = 0; p < PD; p++) {
        float v = partial[p];
        #pragma unroll
        for (int o = 16; o > 0; o >>= 1) v += __shfl_down_sync(0xffffffffu, v, o);
        if ((t & 31) == 0) red[(t >> 5) * PD + p] = v;
    }
    __syncthreads();
    if (t == 0) {
        float sc[PD];
        #pragma unroll
        for (int p = 0; p < PD; p++)
            sc[p] = red[p] + red[PD + p] + red[2 * PD + p] + red[3 * PD + p];
        float mx = fmaxf(sc[0], fmaxf(sc[1], sc[2]));
        float e0 = __expf(sc[0] - mx), e1 = __expf(sc[1] - mx), e2 = __expf(sc[2] - mx);
        float Zs = e0 + e1 + e2;
        al[0] = e0 / Zs; al[1] = e1 / Zs; al[2] = e2 / Zs;
    }
    __syncthreads();

    if (has_alpha && t < PD)
        out[(size_t)ND * (CD + EMB) + (size_t)n * PD + t] = al[t];

    if (t < EMB) {
        float f = al[0] * multi_s[0][t] + al[1] * multi_s[1][t] + al[2] * multi_s[2][t];
        fin[t] = f;
        if (has_final) out[(size_t)ND * CD + (size_t)n * EMB + t] = f;
    }
    __syncthreads();

    if (t < CD) {
        float s = bc[t];
        #pragma unroll
        for (int d = 0; d < EMB; d++) s += fin[d] * Wc[d * CD + t];
        out[(size_t)n * CD + t] = s;
    }
}

// ---------------- launch ------------------------------------------------------
extern "C" void kernel_launch(void* const* d_in, const int* in_sizes, int n_in,
                              void* d_out, int out_size) {
    const float* inputs   = (const float*)d_in[0];
    const float* bias_mat = (const float*)d_in[1];
    const float* W        = (const float*)d_in[2];
    const float* a1_w     = (const float*)d_in[3];
    const float* a1_b     = (const float*)d_in[4];
    const float* a2_w     = (const float*)d_in[5];
    const float* a2_b     = (const float*)d_in[6];
    const float* h_bias   = (const float*)d_in[7];
    const float* Ws       = (const float*)d_in[8];
    const float* bs       = (const float*)d_in[9];
    const float* u        = (const float*)d_in[10];
    const float* Wc       = (const float*)d_in[11];
    const float* bc       = (const float*)d_in[12];
    float* out = (float*)d_out;

    int has_final = (out_size >= ND * (CD + EMB)) ? 1 : 0;
    int has_alpha = (out_size >= ND * (CD + EMB + PD)) ? 1 : 0;

    cudaFuncSetAttribute(k2_attn_mma, cudaFuncAttributeMaxDynamicSharedMemorySize,
                         K2_SMEM);

    k1_gemm    <<<dim3(ND / 64, PD, KSEG), 256>>>(inputs, W);
    k1c_combine<<<dim3(ND / 32, PD), 256>>>(a1_w, a1_b, a2_w, a2_b);
    k2_attn_mma<<<dim3(ND / 128, MSEG, PD), 256, K2_SMEM>>>(bias_mat);
    k3_final   <<<ND, 128>>>(h_bias, Ws, bs, u, Wc, bc, out, has_final, has_alpha);
    (void)in_sizes; (void)n_in;
}